// round 15
// baseline (speedup 1.0000x reference)
#include <cuda_runtime.h>
#include <cuda_fp16.h>
#include <cstdint>

// ---------------------------------------------------------------------------
// Problem constants
// ---------------------------------------------------------------------------
#define NTOK   16384      // B*S
#define DIN    2048
#define DOUT   2048
#define RANK   16
#define NADAPT 8
#define KEXT   (NADAPT*RANK)    // 128
#define KTOT   (DIN + KEXT)     // 2176

// Main GEMM tiling (best measured config, unchanged)
#define BM 256
#define BN 128
#define BKL 128                 // fp16 per chunk = 256 bytes/row
#define NCH (KTOT / BKL)        // 17
#define A_ST (BM * 256)         // 65536
#define B_ST (BN * 256)         // 32768
#define ST_BYTES (A_ST + B_ST)  // 98304
#define SMEM_BYTES (2 * ST_BYTES)   // 196608 (2 stages)

// u_xu smem: 3-stage ring; per stage: x 8KB + A 16KB
#define PX_ST 8192
#define PA_ST 16384
#define P_ST  (PX_ST + PA_ST)              // 24576
#define P_STAGES 3
#define P_SMEM_BYTES (P_STAGES * P_ST)     // 73728
#define NXB (NTOK / 64)                    // 256 u_xu blocks
#define PNCH (DIN / 64)                    // 32 chunks
#define NWB (DOUT / 8)                     // 256 W-conv blocks

// fp16 buffers
__device__ __half g_xh[(size_t)NTOK * KTOT];
__device__ __half g_wh[(size_t)DOUT * KTOT];
__device__ __half g_ah[(size_t)NADAPT * RANK * DIN];   // [128, 2048]

// ---------------------------------------------------------------------------
// Helpers
// ---------------------------------------------------------------------------
__device__ __forceinline__ uint32_t smem_u32(const void* p) {
    uint32_t a;
    asm("{ .reg .u64 t; cvta.to.shared.u64 t, %1; cvt.u32.u64 %0, t; }"
        : "=r"(a) : "l"(p));
    return a;
}

__device__ __forceinline__ void cp_async16(uint32_t dst, const void* src) {
    asm volatile("cp.async.cg.shared.global [%0], [%1], 16;"
                 :: "r"(dst), "l"(src) : "memory");
}

__device__ __forceinline__ void ldsm_x4(uint32_t* r, uint32_t addr) {
    asm volatile("ldmatrix.sync.aligned.m8n8.x4.shared.b16 {%0,%1,%2,%3}, [%4];"
                 : "=r"(r[0]), "=r"(r[1]), "=r"(r[2]), "=r"(r[3]) : "r"(addr));
}

__device__ __forceinline__ void mma_f16_16816(
    float* c, const uint32_t* a, const uint32_t* b)
{
    asm volatile(
        "mma.sync.aligned.m16n8k16.row.col.f32.f16.f16.f32 "
        "{%0,%1,%2,%3}, {%4,%5,%6,%7}, {%8,%9}, {%0,%1,%2,%3};"
        : "+f"(c[0]), "+f"(c[1]), "+f"(c[2]), "+f"(c[3])
        : "r"(a[0]), "r"(a[1]), "r"(a[2]), "r"(a[3]),
          "r"(b[0]), "r"(b[1]));
}

__device__ __forceinline__ uint32_t pack_h2(float x, float y) {
    __half2 h = __float22half2_rn(make_float2(x, y));
    return *reinterpret_cast<uint32_t*>(&h);
}

// ---------------------------------------------------------------------------
// Kernel 0: conv_a — tiny: lora_a fp32 -> g_ah fp16 (262144 floats).
// ---------------------------------------------------------------------------
__global__ void __launch_bounds__(256) conv_a_kernel(const float* __restrict__ lora_a)
{
    size_t i = ((size_t)blockIdx.x * 256 + threadIdx.x) * 4;
    float4 av = *(const float4*)(lora_a + i);
    uint2 ov = make_uint2(pack_h2(av.x, av.y), pack_h2(av.z, av.w));
    *(uint2*)(g_ah + i) = ov;
}

// ---------------------------------------------------------------------------
// Kernel 1: fused prep.
// Blocks [0, 256): u_xu role — phase 1 converts own 64-token x tile into
//   g_xh main cols; phase 2 runs the 3-stage cp.async U-pipeline on its own
//   just-written rows + g_ah, writing scaled/selected U into g_xh ext cols.
// Blocks [256, 512): W-conv role — 8 W rows -> g_wh, lora_b -> ext cols.
// Independent roles interleave on SMs: conversion DRAM traffic overlaps
// U-compute.
// ---------------------------------------------------------------------------
__global__ void __launch_bounds__(256, 3) fused_prep_kernel(
    const float* __restrict__ x,
    const int*   __restrict__ mapping,
    const float* __restrict__ W,
    const float* __restrict__ lora_b,
    const float* __restrict__ scaling)
{
    const int tid  = threadIdx.x;
    const int lane = tid & 31;

    if (blockIdx.x >= NXB) {
        // ---------------- W-conv role ----------------
        const int bw = blockIdx.x - NXB;
        const int o = bw * 8 + (tid >> 5);
        const float* wr = W + (size_t)o * DIN;
        __half* orow = g_wh + (size_t)o * KTOT;
#pragma unroll
        for (int i = 0; i < 16; i++) {
            int seg = lane + i * 32;
            float4 v = *(const float4*)(wr + seg * 4);
            uint2 ov = make_uint2(pack_h2(v.x, v.y), pack_h2(v.z, v.w));
            *(uint2*)(orow + seg * 4) = ov;
        }
        int e0 = lane * 4;
        int a = e0 >> 4;
        int r0 = e0 & 15;
        float4 lb = *(const float4*)(lora_b + ((size_t)a * DOUT + o) * RANK + r0);
        uint2 ov = make_uint2(pack_h2(lb.x, lb.y), pack_h2(lb.z, lb.w));
        *(uint2*)(orow + DIN + e0) = ov;
        return;
    }

    // ---------------- u_xu role ----------------
    extern __shared__ char psmem[];
    const uint32_t sb = smem_u32(psmem);
    const int wid  = tid >> 5;
    const int gid  = lane >> 2;
    const int tig  = lane & 3;
    const int warpM = wid >> 2;     // 0..1 -> 32 token-rows
    const int warpN = wid & 3;      // 0..3 -> 32 U-cols
    const int tBase = blockIdx.x * 64;
    const uint32_t lane7 = lane & 7;

    // ---- Phase 1: convert own x tile (64 rows x 2048) -> g_xh main cols ----
    // 16384 uint4 outputs / 256 threads = 64 per thread
#pragma unroll 4
    for (int j = 0; j < 64; j++) {
        int idx = tid + j * 256;        // 0..16383
        int row = idx >> 8;             // 0..63
        int seg = idx & 255;            // uint4 segment in row
        const float* xp = x + (size_t)(tBase + row) * DIN + seg * 8;
        float4 v0 = *(const float4*)(xp);
        float4 v1 = *(const float4*)(xp + 4);
        uint4 h = make_uint4(pack_h2(v0.x, v0.y), pack_h2(v0.z, v0.w),
                             pack_h2(v1.x, v1.y), pack_h2(v1.z, v1.w));
        *(uint4*)(g_xh + (size_t)(tBase + row) * KTOT + seg * 8) = h;
    }
    __syncthreads();   // all main-col writes visible before phase-2 reads

    // ---- Phase 2: U = x @ A_all^T (3-stage cp.async ring, proven R14) ----
    const int lrow = tid >> 3;      // 0..31
    const int lseg = tid & 7;       // 0..7
    const uint32_t sw_off = (uint32_t)(lseg ^ (lrow & 7)) * 16;

    float acc[2][4][4];
#pragma unroll
    for (int mi = 0; mi < 2; mi++)
#pragma unroll
        for (int ni = 0; ni < 4; ni++)
#pragma unroll
            for (int q = 0; q < 4; q++) acc[mi][ni][q] = 0.0f;

    auto load_stage = [&](int ch) {
        const int s = ch % P_STAGES;
        const uint32_t xbase = sb + s * P_ST;
        const uint32_t abase = xbase + PX_ST;
        const int k0g = ch * 64;
#pragma unroll
        for (int t = 0; t < 2; t++) {
            int row = lrow + t * 32;
            cp_async16(xbase + row * 128 + sw_off,
                       g_xh + (size_t)(tBase + row) * KTOT + k0g + lseg * 8);
        }
#pragma unroll
        for (int t = 0; t < 4; t++) {
            int row = lrow + t * 32;
            cp_async16(abase + row * 128 + sw_off,
                       g_ah + (size_t)row * DIN + k0g + lseg * 8);
        }
        asm volatile("cp.async.commit_group;" ::: "memory");
    };

    const int ra = (lane & 7) + ((lane >> 3) & 1) * 8;
    const int ka = lane >> 4;
    const int rb = (lane & 7) + ((lane >> 4) & 1) * 8;
    const int kb = (lane >> 3) & 1;

    load_stage(0);
    load_stage(1);

    for (int ch = 0; ch < PNCH; ch++) {
        // Drain correctly on the final iteration (only its group may pend).
        if (ch + 1 < PNCH)
            asm volatile("cp.async.wait_group 1;" ::: "memory");
        else
            asm volatile("cp.async.wait_group 0;" ::: "memory");
        __syncthreads();

        if (ch + 2 < PNCH) load_stage(ch + 2);

        const int s = ch % P_STAGES;
        const uint32_t aw = sb + s * P_ST + (warpM * 32) * 128;
        const uint32_t bw = sb + s * P_ST + PX_ST + (warpN * 32) * 128;

#pragma unroll
        for (int ks = 0; ks < 4; ks++) {
            uint32_t af[2][4];
#pragma unroll
            for (int mi = 0; mi < 2; mi++) {
                uint32_t addr = aw + (mi * 16 + ra) * 128
                              + (((uint32_t)(ks * 2 + ka) ^ lane7) * 16);
                ldsm_x4(af[mi], addr);
            }
            uint32_t bf[4][2];
#pragma unroll
            for (int nj = 0; nj < 2; nj++) {
                uint32_t t[4];
                uint32_t addr = bw + (nj * 16 + rb) * 128
                              + (((uint32_t)(ks * 2 + kb) ^ lane7) * 16);
                ldsm_x4(t, addr);
                bf[2 * nj][0] = t[0]; bf[2 * nj][1] = t[1];
                bf[2 * nj + 1][0] = t[2]; bf[2 * nj + 1][1] = t[3];
            }
#pragma unroll
            for (int mi = 0; mi < 2; mi++)
#pragma unroll
                for (int ni = 0; ni < 4; ni++)
                    mma_f16_16816(acc[mi][ni], af[mi], bf[ni]);
        }
        __syncthreads();
    }

    // epilogue: select adapter slice, scale, write ext cols
#pragma unroll
    for (int mi = 0; mi < 2; mi++) {
        const int r0 = warpM * 32 + mi * 16 + gid;
        const int r1 = r0 + 8;
        const int aid0 = mapping[tBase + r0];
        const int aid1 = mapping[tBase + r1];
        const float s0 = (aid0 > 0) ? scaling[aid0 - 1] : 0.0f;
        const float s1 = (aid1 > 0) ? scaling[aid1 - 1] : 0.0f;
#pragma unroll
        for (int ni = 0; ni < 4; ni++) {
            const int col = warpN * 32 + ni * 8 + tig * 2;
            const bool sel0 = (aid0 > 0) && ((col >> 4) == aid0 - 1);
            const bool sel1 = (aid1 > 0) && ((col >> 4) == aid1 - 1);
            uint32_t v0 = sel0 ? pack_h2(acc[mi][ni][0] * s0, acc[mi][ni][1] * s0) : 0u;
            uint32_t v1 = sel1 ? pack_h2(acc[mi][ni][2] * s1, acc[mi][ni][3] * s1) : 0u;
            *(uint32_t*)(g_xh + (size_t)(tBase + r0) * KTOT + DIN + col) = v0;
            *(uint32_t*)(g_xh + (size_t)(tBase + r1) * KTOT + DIN + col) = v1;
        }
    }
}

// ---------------------------------------------------------------------------
// Main GEMM (best measured, unchanged): CTA 256x128, 16 warps (4Mx4N),
// warp tile 64x32, BK=128 (256B rows), 2-stage double buffer.
// ---------------------------------------------------------------------------
__global__ void __launch_bounds__(512, 1) gemm_h_kernel(
    const float* __restrict__ bias, float* __restrict__ out)
{
    extern __shared__ char smem[];
    const uint32_t sb = smem_u32(smem);
    const int tid  = threadIdx.x;
    const int wid  = tid >> 5;
    const int lane = tid & 31;
    const int gid  = lane >> 2;
    const int tig  = lane & 3;
    const int warpM = wid & 3;      // 0..3 -> 64 rows each
    const int warpN = wid >> 2;     // 0..3 -> 32 cols each
    const int mBase = blockIdx.y * BM;
    const int oBase = blockIdx.x * BN;
    const uint32_t lane7 = lane & 7;

    float acc[4][4][4];
#pragma unroll
    for (int mi = 0; mi < 4; mi++)
#pragma unroll
        for (int n = 0; n < 4; n++)
#pragma unroll
            for (int q = 0; q < 4; q++) acc[mi][n][q] = 0.0f;

    const int srow = tid >> 4;      // 0..31
    const int sseg = tid & 15;      // 0..15
    const uint32_t st_off = (uint32_t)(sseg >> 3) * 128
                          + (uint32_t)((sseg & 7) ^ (srow & 7)) * 16;

    auto load_stage = [&](int chunk, int slot) {
        const uint32_t abase = sb + slot * ST_BYTES;
        const uint32_t bbase = abase + A_ST;
        const size_t koff = (size_t)chunk * BKL + sseg * 8;
#pragma unroll
        for (int t = 0; t < 8; t++) {           // A: 256 rows
            int row = srow + t * 32;
            cp_async16(abase + row * 256 + st_off,
                       g_xh + (size_t)(mBase + row) * KTOT + koff);
        }
#pragma unroll
        for (int t = 0; t < 4; t++) {           // B: 128 rows
            int row = srow + t * 32;
            cp_async16(bbase + row * 256 + st_off,
                       g_wh + (size_t)(oBase + row) * KTOT + koff);
        }
        asm volatile("cp.async.commit_group;" ::: "memory");
    };

    load_stage(0, 0);

    const int ra = (lane & 7) + ((lane >> 3) & 1) * 8;
    const int ka = lane >> 4;
    const int rb = (lane & 7) + ((lane >> 4) & 1) * 8;
    const int kb = (lane >> 3) & 1;

    for (int i = 0; i < NCH; i++) {
        asm volatile("cp.async.wait_group 0;" ::: "memory");
        __syncthreads();

        if (i + 1 < NCH) load_stage(i + 1, (i + 1) & 1);

        const int slot = i & 1;
        const uint32_t aw = sb + slot * ST_BYTES + (warpM * 64) * 256;
        const uint32_t bw = sb + slot * ST_BYTES + A_ST + (warpN * 32) * 256;

#pragma unroll
        for (int ks = 0; ks < 8; ks++) {
            const uint32_t sa = (uint32_t)(ks * 2 + ka);
            const uint32_t sb2 = (uint32_t)(ks * 2 + kb);
            const uint32_t aoff = (sa >> 3) * 128 + (((sa & 7) ^ lane7) * 16);
            const uint32_t boff = (sb2 >> 3) * 128 + (((sb2 & 7) ^ lane7) * 16);

            uint32_t af[4][4];
#pragma unroll
            for (int mi = 0; mi < 4; mi++)
                ldsm_x4(af[mi], aw + (mi * 16 + ra) * 256 + aoff);

            uint32_t bf[4][2];
#pragma unroll
            for (int nj = 0; nj < 2; nj++) {
                uint32_t t[4];
                ldsm_x4(t, bw + (nj * 16 + rb) * 256 + boff);
                bf[2 * nj][0] = t[0]; bf[2 * nj][1] = t[1];
                bf[2 * nj + 1][0] = t[2]; bf[2 * nj + 1][1] = t[3];
            }
#pragma unroll
            for (int mi = 0; mi < 4; mi++)
#pragma unroll
                for (int n = 0; n < 4; n++)
                    mma_f16_16816(acc[mi][n], af[mi], bf[n]);
        }
    }

    // epilogue: bias + store
#pragma unroll
    for (int mi = 0; mi < 4; mi++) {
        const int row = mBase + warpM * 64 + mi * 16 + gid;
#pragma unroll
        for (int n = 0; n < 4; n++) {
            const int col = oBase + warpN * 32 + n * 8 + tig * 2;
            float2 b2 = *(const float2*)(bias + col);
            float2 o0, o1;
            o0.x = acc[mi][n][0] + b2.x;
            o0.y = acc[mi][n][1] + b2.y;
            o1.x = acc[mi][n][2] + b2.x;
            o1.y = acc[mi][n][3] + b2.y;
            *(float2*)(out + (size_t)row * DOUT + col) = o0;
            *(float2*)(out + (size_t)(row + 8) * DOUT + col) = o1;
        }
    }
}

// ---------------------------------------------------------------------------
// Inputs: x, lora_mapping, weight, bias, lora_a, lora_b, scaling
// ---------------------------------------------------------------------------
extern "C" void kernel_launch(void* const* d_in, const int* in_sizes, int n_in,
                              void* d_out, int out_size)
{
    const float* x       = (const float*)d_in[0];
    const int*   mapping = (const int*)  d_in[1];
    const float* weight  = (const float*)d_in[2];
    const float* bias    = (const float*)d_in[3];
    const float* lora_a  = (const float*)d_in[4];
    const float* lora_b  = (const float*)d_in[5];
    const float* scaling = (const float*)d_in[6];
    float*       out     = (float*)d_out;

    cudaFuncSetAttribute(gemm_h_kernel,
                         cudaFuncAttributeMaxDynamicSharedMemorySize, SMEM_BYTES);
    cudaFuncSetAttribute(fused_prep_kernel,
                         cudaFuncAttributeMaxDynamicSharedMemorySize, P_SMEM_BYTES);

    conv_a_kernel<<<(NADAPT * RANK * DIN / 4) / 256, 256>>>(lora_a);
    fused_prep_kernel<<<NXB + NWB, 256, P_SMEM_BYTES>>>(
        x, mapping, weight, lora_b, scaling);

    dim3 grid(DOUT / BN, NTOK / BM);
    gemm_h_kernel<<<grid, 512, SMEM_BYTES>>>(bias, out);
}

// round 16
// speedup vs baseline: 1.0482x; 1.0482x over previous
#include <cuda_runtime.h>
#include <cuda_fp16.h>
#include <cstdint>

// ---------------------------------------------------------------------------
// Problem constants
// ---------------------------------------------------------------------------
#define NTOK   16384      // B*S
#define DIN    2048
#define DOUT   2048
#define RANK   16
#define NADAPT 8
#define KEXT   (NADAPT*RANK)    // 128
#define KTOT   (DIN + KEXT)     // 2176

// Main GEMM tiling (best measured config, unchanged)
#define BM 256
#define BN 128
#define BKL 128                 // fp16 per chunk = 256 bytes/row
#define NCH (KTOT / BKL)        // 17
#define A_ST (BM * 256)         // 65536
#define B_ST (BN * 256)         // 32768
#define ST_BYTES (A_ST + B_ST)  // 98304
#define SMEM_BYTES (2 * ST_BYTES)   // 196608 (2 stages)

// u_xu smem: 3-stage ring; per stage: x 8KB + A 16KB
#define PX_ST 8192
#define PA_ST 16384
#define P_ST  (PX_ST + PA_ST)              // 24576
#define P_STAGES 3
#define P_SMEM_BYTES (P_STAGES * P_ST)     // 73728
#define NXB (NTOK / 64)                    // 256 u_xu blocks
#define PNCH (DIN / 64)                    // 32 chunks
#define XCB  (NTOK / 8)                    // 2048 x-conv blocks
#define WCB  (DOUT / 8)                    // 256 W-conv blocks

// fp16 buffers
__device__ __half g_xh[(size_t)NTOK * KTOT];
__device__ __half g_wh[(size_t)DOUT * KTOT];
__device__ __half g_ah[(size_t)NADAPT * RANK * DIN];   // [128, 2048]

// ---------------------------------------------------------------------------
// Helpers
// ---------------------------------------------------------------------------
__device__ __forceinline__ uint32_t smem_u32(const void* p) {
    uint32_t a;
    asm("{ .reg .u64 t; cvta.to.shared.u64 t, %1; cvt.u32.u64 %0, t; }"
        : "=r"(a) : "l"(p));
    return a;
}

__device__ __forceinline__ void cp_async16(uint32_t dst, const void* src) {
    asm volatile("cp.async.cg.shared.global [%0], [%1], 16;"
                 :: "r"(dst), "l"(src) : "memory");
}

__device__ __forceinline__ void ldsm_x4(uint32_t* r, uint32_t addr) {
    asm volatile("ldmatrix.sync.aligned.m8n8.x4.shared.b16 {%0,%1,%2,%3}, [%4];"
                 : "=r"(r[0]), "=r"(r[1]), "=r"(r[2]), "=r"(r[3]) : "r"(addr));
}

__device__ __forceinline__ void mma_f16_16816(
    float* c, const uint32_t* a, const uint32_t* b)
{
    asm volatile(
        "mma.sync.aligned.m16n8k16.row.col.f32.f16.f16.f32 "
        "{%0,%1,%2,%3}, {%4,%5,%6,%7}, {%8,%9}, {%0,%1,%2,%3};"
        : "+f"(c[0]), "+f"(c[1]), "+f"(c[2]), "+f"(c[3])
        : "r"(a[0]), "r"(a[1]), "r"(a[2]), "r"(a[3]),
          "r"(b[0]), "r"(b[1]));
}

__device__ __forceinline__ uint32_t pack_h2(float x, float y) {
    __half2 h = __float22half2_rn(make_float2(x, y));
    return *reinterpret_cast<uint32_t*>(&h);
}

// ---------------------------------------------------------------------------
// Kernel 0: conv_a — tiny: lora_a fp32 -> g_ah fp16.
// ---------------------------------------------------------------------------
__global__ void __launch_bounds__(256) conv_a_kernel(const float* __restrict__ lora_a)
{
    size_t i = ((size_t)blockIdx.x * 256 + threadIdx.x) * 4;
    float4 av = *(const float4*)(lora_a + i);
    uint2 ov = make_uint2(pack_h2(av.x, av.y), pack_h2(av.z, av.w));
    *(uint2*)(g_ah + i) = ov;
}

// ---------------------------------------------------------------------------
// Kernel 1: merged prep — roles by blockIdx, NO inter-role dependency:
//  [0, 256):        u_xu — reads fp32 x directly (in-register convert,
//                   prefetched LDGs) + fp16 g_ah; writes g_xh ext cols.
//  [256, 2304):     x-conv — 8 x rows -> g_xh main cols.
//  [2304, 2560):    W-conv — 8 W rows -> g_wh + lora_b ext cols.
// u_xu blocks first so wave 1 starts U-compute while conv blocks stream DRAM.
// ---------------------------------------------------------------------------
__global__ void __launch_bounds__(256, 3) merged_prep_kernel(
    const float* __restrict__ x,
    const int*   __restrict__ mapping,
    const float* __restrict__ W,
    const float* __restrict__ lora_b,
    const float* __restrict__ scaling)
{
    const int tid  = threadIdx.x;
    const int lane = tid & 31;

    if (blockIdx.x >= NXB) {
        if (blockIdx.x < NXB + XCB) {
            // ---------------- x-conv role ----------------
            const int row = (blockIdx.x - NXB) * 8 + (tid >> 5);
            const float* xr = x + (size_t)row * DIN;
            __half* orow = g_xh + (size_t)row * KTOT;
#pragma unroll
            for (int i = 0; i < 16; i++) {
                int seg = lane + i * 32;
                float4 v = *(const float4*)(xr + seg * 4);
                uint2 ov = make_uint2(pack_h2(v.x, v.y), pack_h2(v.z, v.w));
                *(uint2*)(orow + seg * 4) = ov;
            }
        } else {
            // ---------------- W-conv role ----------------
            const int o = (blockIdx.x - NXB - XCB) * 8 + (tid >> 5);
            const float* wr = W + (size_t)o * DIN;
            __half* orow = g_wh + (size_t)o * KTOT;
#pragma unroll
            for (int i = 0; i < 16; i++) {
                int seg = lane + i * 32;
                float4 v = *(const float4*)(wr + seg * 4);
                uint2 ov = make_uint2(pack_h2(v.x, v.y), pack_h2(v.z, v.w));
                *(uint2*)(orow + seg * 4) = ov;
            }
            int e0 = lane * 4;
            int a = e0 >> 4;
            int r0 = e0 & 15;
            float4 lb = *(const float4*)(lora_b + ((size_t)a * DOUT + o) * RANK + r0);
            uint2 ov = make_uint2(pack_h2(lb.x, lb.y), pack_h2(lb.z, lb.w));
            *(uint2*)(orow + DIN + e0) = ov;
        }
        return;
    }

    // ---------------- u_xu role (fp32 x, register prefetch) ----------------
    extern __shared__ char psmem[];
    const uint32_t sb = smem_u32(psmem);
    const int wid  = tid >> 5;
    const int gid  = lane >> 2;
    const int tig  = lane & 3;
    const int warpM = wid >> 2;     // 0..1 -> 32 token-rows
    const int warpN = wid & 3;      // 0..3 -> 32 U-cols
    const int tBase = blockIdx.x * 64;
    const uint32_t lane7 = lane & 7;

    const int lrow = tid >> 3;      // 0..31
    const int lseg = tid & 7;       // 0..7
    const uint32_t sw_off = (uint32_t)(lseg ^ (lrow & 7)) * 16;

    float acc[2][4][4];
#pragma unroll
    for (int mi = 0; mi < 2; mi++)
#pragma unroll
        for (int ni = 0; ni < 4; ni++)
#pragma unroll
            for (int q = 0; q < 4; q++) acc[mi][ni][q] = 0.0f;

    // x staging: per thread, rows {lrow, lrow+32}, 8 fp32 each -> 4 float4
    auto ldg_x = [&](int ch, float4* xr) {
        const int k0g = ch * 64;
#pragma unroll
        for (int t = 0; t < 2; t++) {
            const float* xp = x + (size_t)(tBase + lrow + t * 32) * DIN
                            + k0g + lseg * 8;
            xr[2 * t]     = *(const float4*)(xp);
            xr[2 * t + 1] = *(const float4*)(xp + 4);
        }
    };
    auto sts_x = [&](int ch, const float4* xr) {
        const int s = ch % P_STAGES;
#pragma unroll
        for (int t = 0; t < 2; t++) {
            uint4 h = make_uint4(
                pack_h2(xr[2 * t].x, xr[2 * t].y),
                pack_h2(xr[2 * t].z, xr[2 * t].w),
                pack_h2(xr[2 * t + 1].x, xr[2 * t + 1].y),
                pack_h2(xr[2 * t + 1].z, xr[2 * t + 1].w));
            *(uint4*)(psmem + s * P_ST + (lrow + t * 32) * 128 + sw_off) = h;
        }
    };
    auto load_A = [&](int ch) {
        const int s = ch % P_STAGES;
        const uint32_t abase = sb + s * P_ST + PX_ST;
        const int k0g = ch * 64;
#pragma unroll
        for (int t = 0; t < 4; t++) {
            int row = lrow + t * 32;
            cp_async16(abase + row * 128 + sw_off,
                       g_ah + (size_t)row * DIN + k0g + lseg * 8);
        }
        asm volatile("cp.async.commit_group;" ::: "memory");
    };

    const int ra = (lane & 7) + ((lane >> 3) & 1) * 8;
    const int ka = lane >> 4;
    const int rb = (lane & 7) + ((lane >> 4) & 1) * 8;
    const int kb = (lane >> 3) & 1;

    // prologue: stage chunks 0 and 1
    {
        float4 xr[4];
        ldg_x(0, xr); sts_x(0, xr); load_A(0);
        ldg_x(1, xr); sts_x(1, xr); load_A(1);
    }

    for (int ch = 0; ch < PNCH; ch++) {
        // Drain rule (R13 lesson): last iteration must wait for ALL groups.
        if (ch + 1 < PNCH)
            asm volatile("cp.async.wait_group 1;" ::: "memory");
        else
            asm volatile("cp.async.wait_group 0;" ::: "memory");
        __syncthreads();

        const bool pf = (ch + 2 < PNCH);
        float4 xr[4];
        if (pf) ldg_x(ch + 2, xr);   // LDGs hide under the mma block below

        const int s = ch % P_STAGES;
        const uint32_t aw = sb + s * P_ST + (warpM * 32) * 128;
        const uint32_t bw = sb + s * P_ST + PX_ST + (warpN * 32) * 128;

#pragma unroll
        for (int ks = 0; ks < 4; ks++) {
            uint32_t af[2][4];
#pragma unroll
            for (int mi = 0; mi < 2; mi++) {
                uint32_t addr = aw + (mi * 16 + ra) * 128
                              + (((uint32_t)(ks * 2 + ka) ^ lane7) * 16);
                ldsm_x4(af[mi], addr);
            }
            uint32_t bf[4][2];
#pragma unroll
            for (int nj = 0; nj < 2; nj++) {
                uint32_t t[4];
                uint32_t addr = bw + (nj * 16 + rb) * 128
                              + (((uint32_t)(ks * 2 + kb) ^ lane7) * 16);
                ldsm_x4(t, addr);
                bf[2 * nj][0] = t[0]; bf[2 * nj][1] = t[1];
                bf[2 * nj + 1][0] = t[2]; bf[2 * nj + 1][1] = t[3];
            }
#pragma unroll
            for (int mi = 0; mi < 2; mi++)
#pragma unroll
                for (int ni = 0; ni < 4; ni++)
                    mma_f16_16816(acc[mi][ni], af[mi], bf[ni]);
        }

        if (pf) { sts_x(ch + 2, xr); load_A(ch + 2); }
        __syncthreads();   // protects slot (ch%3) from next iteration's writers
    }

    // epilogue: select adapter slice, scale, write ext cols
#pragma unroll
    for (int mi = 0; mi < 2; mi++) {
        const int r0 = warpM * 32 + mi * 16 + gid;
        const int r1 = r0 + 8;
        const int aid0 = mapping[tBase + r0];
        const int aid1 = mapping[tBase + r1];
        const float s0 = (aid0 > 0) ? scaling[aid0 - 1] : 0.0f;
        const float s1 = (aid1 > 0) ? scaling[aid1 - 1] : 0.0f;
#pragma unroll
        for (int ni = 0; ni < 4; ni++) {
            const int col = warpN * 32 + ni * 8 + tig * 2;
            const bool sel0 = (aid0 > 0) && ((col >> 4) == aid0 - 1);
            const bool sel1 = (aid1 > 0) && ((col >> 4) == aid1 - 1);
            uint32_t v0 = sel0 ? pack_h2(acc[mi][ni][0] * s0, acc[mi][ni][1] * s0) : 0u;
            uint32_t v1 = sel1 ? pack_h2(acc[mi][ni][2] * s1, acc[mi][ni][3] * s1) : 0u;
            *(uint32_t*)(g_xh + (size_t)(tBase + r0) * KTOT + DIN + col) = v0;
            *(uint32_t*)(g_xh + (size_t)(tBase + r1) * KTOT + DIN + col) = v1;
        }
    }
}

// ---------------------------------------------------------------------------
// Main GEMM (best measured, unchanged): CTA 256x128, 16 warps (4Mx4N),
// warp tile 64x32, BK=128 (256B rows), 2-stage double buffer.
// ---------------------------------------------------------------------------
__global__ void __launch_bounds__(512, 1) gemm_h_kernel(
    const float* __restrict__ bias, float* __restrict__ out)
{
    extern __shared__ char smem[];
    const uint32_t sb = smem_u32(smem);
    const int tid  = threadIdx.x;
    const int wid  = tid >> 5;
    const int lane = tid & 31;
    const int gid  = lane >> 2;
    const int tig  = lane & 3;
    const int warpM = wid & 3;      // 0..3 -> 64 rows each
    const int warpN = wid >> 2;     // 0..3 -> 32 cols each
    const int mBase = blockIdx.y * BM;
    const int oBase = blockIdx.x * BN;
    const uint32_t lane7 = lane & 7;

    float acc[4][4][4];
#pragma unroll
    for (int mi = 0; mi < 4; mi++)
#pragma unroll
        for (int n = 0; n < 4; n++)
#pragma unroll
            for (int q = 0; q < 4; q++) acc[mi][n][q] = 0.0f;

    const int srow = tid >> 4;      // 0..31
    const int sseg = tid & 15;      // 0..15
    const uint32_t st_off = (uint32_t)(sseg >> 3) * 128
                          + (uint32_t)((sseg & 7) ^ (srow & 7)) * 16;

    auto load_stage = [&](int chunk, int slot) {
        const uint32_t abase = sb + slot * ST_BYTES;
        const uint32_t bbase = abase + A_ST;
        const size_t koff = (size_t)chunk * BKL + sseg * 8;
#pragma unroll
        for (int t = 0; t < 8; t++) {           // A: 256 rows
            int row = srow + t * 32;
            cp_async16(abase + row * 256 + st_off,
                       g_xh + (size_t)(mBase + row) * KTOT + koff);
        }
#pragma unroll
        for (int t = 0; t < 4; t++) {           // B: 128 rows
            int row = srow + t * 32;
            cp_async16(bbase + row * 256 + st_off,
                       g_wh + (size_t)(oBase + row) * KTOT + koff);
        }
        asm volatile("cp.async.commit_group;" ::: "memory");
    };

    load_stage(0, 0);

    const int ra = (lane & 7) + ((lane >> 3) & 1) * 8;
    const int ka = lane >> 4;
    const int rb = (lane & 7) + ((lane >> 4) & 1) * 8;
    const int kb = (lane >> 3) & 1;

    for (int i = 0; i < NCH; i++) {
        asm volatile("cp.async.wait_group 0;" ::: "memory");
        __syncthreads();

        if (i + 1 < NCH) load_stage(i + 1, (i + 1) & 1);

        const int slot = i & 1;
        const uint32_t aw = sb + slot * ST_BYTES + (warpM * 64) * 256;
        const uint32_t bw = sb + slot * ST_BYTES + A_ST + (warpN * 32) * 256;

#pragma unroll
        for (int ks = 0; ks < 8; ks++) {
            const uint32_t sa = (uint32_t)(ks * 2 + ka);
            const uint32_t sb2 = (uint32_t)(ks * 2 + kb);
            const uint32_t aoff = (sa >> 3) * 128 + (((sa & 7) ^ lane7) * 16);
            const uint32_t boff = (sb2 >> 3) * 128 + (((sb2 & 7) ^ lane7) * 16);

            uint32_t af[4][4];
#pragma unroll
            for (int mi = 0; mi < 4; mi++)
                ldsm_x4(af[mi], aw + (mi * 16 + ra) * 256 + aoff);

            uint32_t bf[4][2];
#pragma unroll
            for (int nj = 0; nj < 2; nj++) {
                uint32_t t[4];
                ldsm_x4(t, bw + (nj * 16 + rb) * 256 + boff);
                bf[2 * nj][0] = t[0]; bf[2 * nj][1] = t[1];
                bf[2 * nj + 1][0] = t[2]; bf[2 * nj + 1][1] = t[3];
            }
#pragma unroll
            for (int mi = 0; mi < 4; mi++)
#pragma unroll
                for (int n = 0; n < 4; n++)
                    mma_f16_16816(acc[mi][n], af[mi], bf[n]);
        }
    }

    // epilogue: bias + store
#pragma unroll
    for (int mi = 0; mi < 4; mi++) {
        const int row = mBase + warpM * 64 + mi * 16 + gid;
#pragma unroll
        for (int n = 0; n < 4; n++) {
            const int col = oBase + warpN * 32 + n * 8 + tig * 2;
            float2 b2 = *(const float2*)(bias + col);
            float2 o0, o1;
            o0.x = acc[mi][n][0] + b2.x;
            o0.y = acc[mi][n][1] + b2.y;
            o1.x = acc[mi][n][2] + b2.x;
            o1.y = acc[mi][n][3] + b2.y;
            *(float2*)(out + (size_t)row * DOUT + col) = o0;
            *(float2*)(out + (size_t)(row + 8) * DOUT + col) = o1;
        }
    }
}

// ---------------------------------------------------------------------------
// Inputs: x, lora_mapping, weight, bias, lora_a, lora_b, scaling
// ---------------------------------------------------------------------------
extern "C" void kernel_launch(void* const* d_in, const int* in_sizes, int n_in,
                              void* d_out, int out_size)
{
    const float* x       = (const float*)d_in[0];
    const int*   mapping = (const int*)  d_in[1];
    const float* weight  = (const float*)d_in[2];
    const float* bias    = (const float*)d_in[3];
    const float* lora_a  = (const float*)d_in[4];
    const float* lora_b  = (const float*)d_in[5];
    const float* scaling = (const float*)d_in[6];
    float*       out     = (float*)d_out;

    cudaFuncSetAttribute(gemm_h_kernel,
                         cudaFuncAttributeMaxDynamicSharedMemorySize, SMEM_BYTES);
    cudaFuncSetAttribute(merged_prep_kernel,
                         cudaFuncAttributeMaxDynamicSharedMemorySize, P_SMEM_BYTES);

    conv_a_kernel<<<(NADAPT * RANK * DIN / 4) / 256, 256>>>(lora_a);
    merged_prep_kernel<<<NXB + XCB + WCB, 256, P_SMEM_BYTES>>>(
        x, mapping, weight, lora_b, scaling);

    dim3 grid(DOUT / BN, NTOK / BM);
    gemm_h_kernel<<<grid, 512, SMEM_BYTES>>>(bias, out);
}

// round 17
// speedup vs baseline: 1.0899x; 1.0398x over previous
#include <cuda_runtime.h>
#include <cuda_fp16.h>
#include <cstdint>

// ---------------------------------------------------------------------------
// Problem constants
// ---------------------------------------------------------------------------
#define NTOK   16384      // B*S
#define DIN    2048
#define DOUT   2048
#define RANK   16
#define NADAPT 8
#define KEXT   (NADAPT*RANK)    // 128
#define KTOT   (DIN + KEXT)     // 2176

// Main GEMM tiling (best measured config, unchanged from R14)
#define BM 256
#define BN 128
#define BKL 128                 // fp16 per chunk = 256 bytes/row
#define NCH (KTOT / BKL)        // 17
#define A_ST (BM * 256)         // 65536
#define B_ST (BN * 256)         // 32768
#define ST_BYTES (A_ST + B_ST)  // 98304
#define SMEM_BYTES (2 * ST_BYTES)   // 196608 (2 stages)

// u_xu smem: 4-stage ring; per stage: x 8KB + A 16KB
#define PX_ST 8192
#define PA_ST 16384
#define P_ST  (PX_ST + PA_ST)              // 24576
#define P_STAGES 4
#define P_SMEM_BYTES (P_STAGES * P_ST)     // 98304 -> 2 CTAs/SM
#define NXB (NTOK / 64)                    // 256 u_xu blocks
#define PNCH (DIN / 64)                    // 32 chunks

// conv_all block split
#define XCONV_BLOCKS (NTOK / 8)            // 2048 (8 x-rows per block)
#define WCONV_BLOCKS (DOUT / 8)            // 256

// fp16 buffers
__device__ __half g_xh[(size_t)NTOK * KTOT];
__device__ __half g_wh[(size_t)DOUT * KTOT];
__device__ __half g_ah[(size_t)NADAPT * RANK * DIN];   // [128, 2048]

// ---------------------------------------------------------------------------
// Helpers
// ---------------------------------------------------------------------------
__device__ __forceinline__ uint32_t smem_u32(const void* p) {
    uint32_t a;
    asm("{ .reg .u64 t; cvta.to.shared.u64 t, %1; cvt.u32.u64 %0, t; }"
        : "=r"(a) : "l"(p));
    return a;
}

__device__ __forceinline__ void cp_async16(uint32_t dst, const void* src) {
    asm volatile("cp.async.cg.shared.global [%0], [%1], 16;"
                 :: "r"(dst), "l"(src) : "memory");
}

__device__ __forceinline__ void ldsm_x4(uint32_t* r, uint32_t addr) {
    asm volatile("ldmatrix.sync.aligned.m8n8.x4.shared.b16 {%0,%1,%2,%3}, [%4];"
                 : "=r"(r[0]), "=r"(r[1]), "=r"(r[2]), "=r"(r[3]) : "r"(addr));
}

__device__ __forceinline__ void mma_f16_16816(
    float* c, const uint32_t* a, const uint32_t* b)
{
    asm volatile(
        "mma.sync.aligned.m16n8k16.row.col.f32.f16.f16.f32 "
        "{%0,%1,%2,%3}, {%4,%5,%6,%7}, {%8,%9}, {%0,%1,%2,%3};"
        : "+f"(c[0]), "+f"(c[1]), "+f"(c[2]), "+f"(c[3])
        : "r"(a[0]), "r"(a[1]), "r"(a[2]), "r"(a[3]),
          "r"(b[0]), "r"(b[1]));
}

__device__ __forceinline__ uint32_t pack_h2(float x, float y) {
    __half2 h = __float22half2_rn(make_float2(x, y));
    return *reinterpret_cast<uint32_t*>(&h);
}

// ---------------------------------------------------------------------------
// Kernel 1: conv_all — pure-bandwidth fp32->fp16 conversions (at DRAM floor).
// ---------------------------------------------------------------------------
__global__ void __launch_bounds__(256) conv_all_kernel(
    const float* __restrict__ x,
    const float* __restrict__ W,
    const float* __restrict__ lora_a,
    const float* __restrict__ lora_b)
{
    const int tid  = threadIdx.x;
    const int lane = tid & 31;
    const int wid  = tid >> 5;

    if (blockIdx.x < XCONV_BLOCKS) {
        const int row = blockIdx.x * 8 + wid;
        const float* xr = x + (size_t)row * DIN;
        __half* orow = g_xh + (size_t)row * KTOT;
#pragma unroll
        for (int i = 0; i < 16; i++) {
            int seg = lane + i * 32;
            float4 v = *(const float4*)(xr + seg * 4);
            uint2 ov = make_uint2(pack_h2(v.x, v.y), pack_h2(v.z, v.w));
            *(uint2*)(orow + seg * 4) = ov;
        }
        return;
    }

    const int bw = blockIdx.x - XCONV_BLOCKS;
    const int o = bw * 8 + wid;
    const float* wr = W + (size_t)o * DIN;
    __half* orow = g_wh + (size_t)o * KTOT;
#pragma unroll
    for (int i = 0; i < 16; i++) {
        int seg = lane + i * 32;
        float4 v = *(const float4*)(wr + seg * 4);
        uint2 ov = make_uint2(pack_h2(v.x, v.y), pack_h2(v.z, v.w));
        *(uint2*)(orow + seg * 4) = ov;
    }
    {   // lora_b ext cols for this W row
        int e0 = lane * 4;
        int a = e0 >> 4;
        int r0 = e0 & 15;
        float4 lb = *(const float4*)(lora_b + ((size_t)a * DOUT + o) * RANK + r0);
        uint2 ov = make_uint2(pack_h2(lb.x, lb.y), pack_h2(lb.z, lb.w));
        *(uint2*)(orow + DIN + e0) = ov;
    }
    {   // lora_a slice: 4 floats per thread
        size_t i = ((size_t)bw * 256 + tid) * 4;
        float4 av = *(const float4*)(lora_a + i);
        uint2 ov = make_uint2(pack_h2(av.x, av.y), pack_h2(av.z, av.w));
        *(uint2*)(g_ah + i) = ov;
    }
}

// ---------------------------------------------------------------------------
// Kernel 2: u_xu — 256 blocks, 64-token tiles, 4-stage cp.async ring
// (3 chunks in flight; wait_group steps down 2->1->0 at the tail — the
// generalized R13 drain rule). Reads fp16 g_xh + g_ah;
// U = x @ A_all^T via ldmatrix+mma; ext cols of g_xh = select(aid)*scale*U.
// ---------------------------------------------------------------------------
__global__ void __launch_bounds__(256, 2) u_xu_kernel(
    const int*   __restrict__ mapping,
    const float* __restrict__ scaling)
{
    extern __shared__ char psmem[];
    const uint32_t sb = smem_u32(psmem);
    const int tid  = threadIdx.x;
    const int lane = tid & 31;
    const int wid  = tid >> 5;
    const int gid  = lane >> 2;
    const int tig  = lane & 3;
    const int warpM = wid >> 2;     // 0..1 -> 32 token-rows
    const int warpN = wid & 3;      // 0..3 -> 32 U-cols
    const int tBase = blockIdx.x * 64;
    const uint32_t lane7 = lane & 7;

    const int lrow = tid >> 3;      // 0..31
    const int lseg = tid & 7;       // 0..7
    const uint32_t sw_off = (uint32_t)(lseg ^ (lrow & 7)) * 16;

    float acc[2][4][4];
#pragma unroll
    for (int mi = 0; mi < 2; mi++)
#pragma unroll
        for (int ni = 0; ni < 4; ni++)
#pragma unroll
            for (int q = 0; q < 4; q++) acc[mi][ni][q] = 0.0f;

    auto load_stage = [&](int ch) {
        const int s = ch % P_STAGES;
        const uint32_t xbase = sb + s * P_ST;
        const uint32_t abase = xbase + PX_ST;
        const int k0g = ch * 64;
#pragma unroll
        for (int t = 0; t < 2; t++) {
            int row = lrow + t * 32;
            cp_async16(xbase + row * 128 + sw_off,
                       g_xh + (size_t)(tBase + row) * KTOT + k0g + lseg * 8);
        }
#pragma unroll
        for (int t = 0; t < 4; t++) {
            int row = lrow + t * 32;
            cp_async16(abase + row * 128 + sw_off,
                       g_ah + (size_t)row * DIN + k0g + lseg * 8);
        }
        asm volatile("cp.async.commit_group;" ::: "memory");
    };

    const int ra = (lane & 7) + ((lane >> 3) & 1) * 8;
    const int ka = lane >> 4;
    const int rb = (lane & 7) + ((lane >> 4) & 1) * 8;
    const int kb = (lane >> 3) & 1;

    load_stage(0);
    load_stage(1);
    load_stage(2);

    for (int ch = 0; ch < PNCH; ch++) {
        // Drain rule: chunk ch must be complete. Pending groups at this
        // point are at most {ch, ch+1, ch+2}; at the tail fewer remain.
        const int rem = PNCH - 1 - ch;   // loads issued beyond ch
        if (rem >= 2)
            asm volatile("cp.async.wait_group 2;" ::: "memory");
        else if (rem == 1)
            asm volatile("cp.async.wait_group 1;" ::: "memory");
        else
            asm volatile("cp.async.wait_group 0;" ::: "memory");
        __syncthreads();

        if (ch + 3 < PNCH) load_stage(ch + 3);

        const int s = ch % P_STAGES;
        const uint32_t aw = sb + s * P_ST + (warpM * 32) * 128;
        const uint32_t bw = sb + s * P_ST + PX_ST + (warpN * 32) * 128;

#pragma unroll
        for (int ks = 0; ks < 4; ks++) {
            uint32_t af[2][4];
#pragma unroll
            for (int mi = 0; mi < 2; mi++) {
                uint32_t addr = aw + (mi * 16 + ra) * 128
                              + (((uint32_t)(ks * 2 + ka) ^ lane7) * 16);
                ldsm_x4(af[mi], addr);
            }
            uint32_t bf[4][2];
#pragma unroll
            for (int nj = 0; nj < 2; nj++) {
                uint32_t t[4];
                uint32_t addr = bw + (nj * 16 + rb) * 128
                              + (((uint32_t)(ks * 2 + kb) ^ lane7) * 16);
                ldsm_x4(t, addr);
                bf[2 * nj][0] = t[0]; bf[2 * nj][1] = t[1];
                bf[2 * nj + 1][0] = t[2]; bf[2 * nj + 1][1] = t[3];
            }
#pragma unroll
            for (int mi = 0; mi < 2; mi++)
#pragma unroll
                for (int ni = 0; ni < 4; ni++)
                    mma_f16_16816(acc[mi][ni], af[mi], bf[ni]);
        }
        __syncthreads();
    }

    // epilogue: select adapter slice, scale, write ext cols
#pragma unroll
    for (int mi = 0; mi < 2; mi++) {
        const int r0 = warpM * 32 + mi * 16 + gid;
        const int r1 = r0 + 8;
        const int aid0 = mapping[tBase + r0];
        const int aid1 = mapping[tBase + r1];
        const float s0 = (aid0 > 0) ? scaling[aid0 - 1] : 0.0f;
        const float s1 = (aid1 > 0) ? scaling[aid1 - 1] : 0.0f;
#pragma unroll
        for (int ni = 0; ni < 4; ni++) {
            const int col = warpN * 32 + ni * 8 + tig * 2;
            const bool sel0 = (aid0 > 0) && ((col >> 4) == aid0 - 1);
            const bool sel1 = (aid1 > 0) && ((col >> 4) == aid1 - 1);
            uint32_t v0 = sel0 ? pack_h2(acc[mi][ni][0] * s0, acc[mi][ni][1] * s0) : 0u;
            uint32_t v1 = sel1 ? pack_h2(acc[mi][ni][2] * s1, acc[mi][ni][3] * s1) : 0u;
            *(uint32_t*)(g_xh + (size_t)(tBase + r0) * KTOT + DIN + col) = v0;
            *(uint32_t*)(g_xh + (size_t)(tBase + r1) * KTOT + DIN + col) = v1;
        }
    }
}

// ---------------------------------------------------------------------------
// Main GEMM (best measured, unchanged from R14): CTA 256x128, 16 warps
// (4Mx4N), warp tile 64x32, BK=128 (256B rows), 2-stage double buffer.
// ---------------------------------------------------------------------------
__global__ void __launch_bounds__(512, 1) gemm_h_kernel(
    const float* __restrict__ bias, float* __restrict__ out)
{
    extern __shared__ char smem[];
    const uint32_t sb = smem_u32(smem);
    const int tid  = threadIdx.x;
    const int wid  = tid >> 5;
    const int lane = tid & 31;
    const int gid  = lane >> 2;
    const int tig  = lane & 3;
    const int warpM = wid & 3;      // 0..3 -> 64 rows each
    const int warpN = wid >> 2;     // 0..3 -> 32 cols each
    const int mBase = blockIdx.y * BM;
    const int oBase = blockIdx.x * BN;
    const uint32_t lane7 = lane & 7;

    float acc[4][4][4];
#pragma unroll
    for (int mi = 0; mi < 4; mi++)
#pragma unroll
        for (int n = 0; n < 4; n++)
#pragma unroll
            for (int q = 0; q < 4; q++) acc[mi][n][q] = 0.0f;

    const int srow = tid >> 4;      // 0..31
    const int sseg = tid & 15;      // 0..15
    const uint32_t st_off = (uint32_t)(sseg >> 3) * 128
                          + (uint32_t)((sseg & 7) ^ (srow & 7)) * 16;

    auto load_stage = [&](int chunk, int slot) {
        const uint32_t abase = sb + slot * ST_BYTES;
        const uint32_t bbase = abase + A_ST;
        const size_t koff = (size_t)chunk * BKL + sseg * 8;
#pragma unroll
        for (int t = 0; t < 8; t++) {           // A: 256 rows
            int row = srow + t * 32;
            cp_async16(abase + row * 256 + st_off,
                       g_xh + (size_t)(mBase + row) * KTOT + koff);
        }
#pragma unroll
        for (int t = 0; t < 4; t++) {           // B: 128 rows
            int row = srow + t * 32;
            cp_async16(bbase + row * 256 + st_off,
                       g_wh + (size_t)(oBase + row) * KTOT + koff);
        }
        asm volatile("cp.async.commit_group;" ::: "memory");
    };

    load_stage(0, 0);

    const int ra = (lane & 7) + ((lane >> 3) & 1) * 8;
    const int ka = lane >> 4;
    const int rb = (lane & 7) + ((lane >> 4) & 1) * 8;
    const int kb = (lane >> 3) & 1;

    for (int i = 0; i < NCH; i++) {
        asm volatile("cp.async.wait_group 0;" ::: "memory");
        __syncthreads();

        if (i + 1 < NCH) load_stage(i + 1, (i + 1) & 1);

        const int slot = i & 1;
        const uint32_t aw = sb + slot * ST_BYTES + (warpM * 64) * 256;
        const uint32_t bw = sb + slot * ST_BYTES + A_ST + (warpN * 32) * 256;

#pragma unroll
        for (int ks = 0; ks < 8; ks++) {
            const uint32_t sa = (uint32_t)(ks * 2 + ka);
            const uint32_t sb2 = (uint32_t)(ks * 2 + kb);
            const uint32_t aoff = (sa >> 3) * 128 + (((sa & 7) ^ lane7) * 16);
            const uint32_t boff = (sb2 >> 3) * 128 + (((sb2 & 7) ^ lane7) * 16);

            uint32_t af[4][4];
#pragma unroll
            for (int mi = 0; mi < 4; mi++)
                ldsm_x4(af[mi], aw + (mi * 16 + ra) * 256 + aoff);

            uint32_t bf[4][2];
#pragma unroll
            for (int nj = 0; nj < 2; nj++) {
                uint32_t t[4];
                ldsm_x4(t, bw + (nj * 16 + rb) * 256 + boff);
                bf[2 * nj][0] = t[0]; bf[2 * nj][1] = t[1];
                bf[2 * nj + 1][0] = t[2]; bf[2 * nj + 1][1] = t[3];
            }
#pragma unroll
            for (int mi = 0; mi < 4; mi++)
#pragma unroll
                for (int n = 0; n < 4; n++)
                    mma_f16_16816(acc[mi][n], af[mi], bf[n]);
        }
    }

    // epilogue: bias + store
#pragma unroll
    for (int mi = 0; mi < 4; mi++) {
        const int row = mBase + warpM * 64 + mi * 16 + gid;
#pragma unroll
        for (int n = 0; n < 4; n++) {
            const int col = oBase + warpN * 32 + n * 8 + tig * 2;
            float2 b2 = *(const float2*)(bias + col);
            float2 o0, o1;
            o0.x = acc[mi][n][0] + b2.x;
            o0.y = acc[mi][n][1] + b2.y;
            o1.x = acc[mi][n][2] + b2.x;
            o1.y = acc[mi][n][3] + b2.y;
            *(float2*)(out + (size_t)row * DOUT + col) = o0;
            *(float2*)(out + (size_t)(row + 8) * DOUT + col) = o1;
        }
    }
}

// ---------------------------------------------------------------------------
// Inputs: x, lora_mapping, weight, bias, lora_a, lora_b, scaling
// ---------------------------------------------------------------------------
extern "C" void kernel_launch(void* const* d_in, const int* in_sizes, int n_in,
                              void* d_out, int out_size)
{
    const float* x       = (const float*)d_in[0];
    const int*   mapping = (const int*)  d_in[1];
    const float* weight  = (const float*)d_in[2];
    const float* bias    = (const float*)d_in[3];
    const float* lora_a  = (const float*)d_in[4];
    const float* lora_b  = (const float*)d_in[5];
    const float* scaling = (const float*)d_in[6];
    float*       out     = (float*)d_out;

    cudaFuncSetAttribute(gemm_h_kernel,
                         cudaFuncAttributeMaxDynamicSharedMemorySize, SMEM_BYTES);
    cudaFuncSetAttribute(u_xu_kernel,
                         cudaFuncAttributeMaxDynamicSharedMemorySize, P_SMEM_BYTES);

    conv_all_kernel<<<XCONV_BLOCKS + WCONV_BLOCKS, 256>>>(x, weight, lora_a, lora_b);
    u_xu_kernel<<<NXB, 256, P_SMEM_BYTES>>>(mapping, scaling);

    dim3 grid(DOUT / BN, NTOK / BM);
    gemm_h_kernel<<<grid, 512, SMEM_BYTES>>>(bias, out);
}